// round 8
// baseline (speedup 1.0000x reference)
#include <cuda_runtime.h>
#include <math.h>

#define Bv 32
#define Nv 512
#define Hv 128
#define NHv 8
#define HDv 16
#define FFv 512
#define NBINS 50
#define ROWS (Bv*Nv)   // 16384

typedef unsigned long long u64;

// ---------------- packed fp32x2 helpers (sm_103a FFMA2 path) ----------------
__device__ __forceinline__ u64 pack2(float x, float y){
    u64 r; asm("mov.b64 %0, {%1, %2};" : "=l"(r) : "f"(x), "f"(y)); return r;
}
__device__ __forceinline__ void unpack2(u64 v, float& x, float& y){
    asm("mov.b64 {%0, %1}, %2;" : "=f"(x), "=f"(y) : "l"(v));
}
__device__ __forceinline__ void fma2(u64& c, u64 a, u64 b){
    asm("fma.rn.f32x2 %0, %1, %2, %3;" : "=l"(c) : "l"(a), "l"(b), "l"(c));
}
__device__ __forceinline__ u64 mul2(u64 a, u64 b){
    u64 r; asm("mul.rn.f32x2 %0, %1, %2;" : "=l"(r) : "l"(a), "l"(b)); return r;
}

// ---------------- scratch (no allocations allowed) ----------------
__device__ float g_hn[ROWS*Hv];
__device__ float g_q [ROWS*Hv];
__device__ float g_k [ROWS*Hv];
__device__ float g_v [ROWS*Hv];
__device__ float g_ao[ROWS*Hv];
__device__ float g_u [ROWS*2*FFv];
__device__ unsigned char g_bins[(size_t)ROWS*Nv];   // 8.4 MB, fits L2

// ---------------- distance->bin precompute (once per launch) ----------------
__global__ __launch_bounds__(256) void bins_kernel(
    const float* __restrict__ dist, unsigned char* __restrict__ bins)
{
    int i = (blockIdx.x*256 + threadIdx.x) * 4;
    float4 d = *(const float4*)(dist + i);
    int b0 = (int)(d.x*10.f); b0 = b0<0?0:(b0>NBINS-1?NBINS-1:b0);
    int b1 = (int)(d.y*10.f); b1 = b1<0?0:(b1>NBINS-1?NBINS-1:b1);
    int b2 = (int)(d.z*10.f); b2 = b2<0?0:(b2>NBINS-1?NBINS-1:b2);
    int b3 = (int)(d.w*10.f); b3 = b3<0?0:(b3>NBINS-1?NBINS-1:b3);
    uchar4 o; o.x=(unsigned char)b0; o.y=(unsigned char)b1;
    o.z=(unsigned char)b2; o.w=(unsigned char)b3;
    *(uchar4*)(bins + i) = o;
}

// ---------------- LayerNorm: one warp per 128-wide row ----------------
__global__ __launch_bounds__(256) void ln_kernel(
    const float* __restrict__ h,
    const float* __restrict__ gamma,
    const float* __restrict__ beta,
    float* __restrict__ out)
{
    int row  = blockIdx.x * 8 + (threadIdx.x >> 5);
    int lane = threadIdx.x & 31;
    const float4* hp = (const float4*)(h + (size_t)row * Hv);
    float4 v = hp[lane];
    float s  = v.x + v.y + v.z + v.w;
    float ss = v.x*v.x + v.y*v.y + v.z*v.z + v.w*v.w;
    #pragma unroll
    for (int off = 16; off; off >>= 1) {
        s  += __shfl_xor_sync(0xffffffffu, s,  off);
        ss += __shfl_xor_sync(0xffffffffu, ss, off);
    }
    float mu  = s * (1.0f/Hv);
    float var = ss * (1.0f/Hv) - mu*mu;
    float inv = rsqrtf(var + 1e-5f);
    float4 g4 = ((const float4*)gamma)[lane];
    float4 b4 = ((const float4*)beta)[lane];
    float4 o;
    o.x = (v.x-mu)*inv*g4.x + b4.x;
    o.y = (v.y-mu)*inv*g4.y + b4.y;
    o.z = (v.z-mu)*inv*g4.z + b4.z;
    o.w = (v.w-mu)*inv*g4.w + b4.w;
    ((float4*)(out + (size_t)row*Hv))[lane] = o;
}

// ---------------- SGEMM: 128x128 tile, BK=16, 8x8 micro-tile, f32x2 FMA ----
// MODE: 0 = plain, 1 = +residual, 2 = GLU(A)+residual, 3 = fused QKV (3 W/b/C)
template<int MODE>
__global__ __launch_bounds__(256) void gemm_kernel(
    const float* __restrict__ A,
    const float* __restrict__ W0, const float* __restrict__ B0, float* __restrict__ C0,
    const float* __restrict__ W1, const float* __restrict__ B1c, float* __restrict__ C1,
    const float* __restrict__ W2, const float* __restrict__ B2c, float* __restrict__ C2,
    const float* __restrict__ R, int K, int Nc)
{
    __shared__ __align__(16) float As[2][16][132];
    __shared__ __align__(16) float Ws[2][16][128];
    const int tid = threadIdx.x;
    const float *W, *bias; float* C;
    int bn;
    if (MODE == 3) {
        int s = blockIdx.x;
        W    = (s==0)?W0:((s==1)?W1:W2);
        bias = (s==0)?B0:((s==1)?B1c:B2c);
        C    = (s==0)?C0:((s==1)?C1:C2);
        bn = 0;
    } else { W = W0; bias = B0; C = C0; bn = blockIdx.x * 128; }
    const int bm = blockIdx.y * 128;
    const int tx = tid & 15, ty = tid >> 4;
    const int ar = tid >> 1, ac = (tid & 1) * 8;   // A loader: row ar, 8 cols
    const int wr = tid >> 4, wc = (tid & 15) * 8;  // W loader: row wr, 8 cols
    const int ldA = (MODE==2) ? (2*FFv) : K;
    const float* Arow = A + (size_t)(bm + ar) * ldA;
    const float* Wp   = W + (size_t)wr * Nc + bn + wc;

    u64 acc[8][4];
    #pragma unroll
    for (int i=0;i<8;i++)
        #pragma unroll
        for (int j=0;j<4;j++) acc[i][j] = 0ull;

    float4 a0v, a1v, w0v, w1v;
    #define LOADT(k0) do { \
        if (MODE==2) { \
            float4 p0 = *(const float4*)(Arow + (k0) + ac); \
            float4 p1 = *(const float4*)(Arow + (k0) + ac + 4); \
            float4 s0 = *(const float4*)(Arow + FFv + (k0) + ac); \
            float4 s1 = *(const float4*)(Arow + FFv + (k0) + ac + 4); \
            a0v.x = p0.x/(1.f+__expf(-s0.x)); a0v.y = p0.y/(1.f+__expf(-s0.y)); \
            a0v.z = p0.z/(1.f+__expf(-s0.z)); a0v.w = p0.w/(1.f+__expf(-s0.w)); \
            a1v.x = p1.x/(1.f+__expf(-s1.x)); a1v.y = p1.y/(1.f+__expf(-s1.y)); \
            a1v.z = p1.z/(1.f+__expf(-s1.z)); a1v.w = p1.w/(1.f+__expf(-s1.w)); \
        } else { \
            a0v = *(const float4*)(Arow + (k0) + ac); \
            a1v = *(const float4*)(Arow + (k0) + ac + 4); \
        } \
        w0v = *(const float4*)(Wp + (size_t)(k0)*Nc); \
        w1v = *(const float4*)(Wp + (size_t)(k0)*Nc + 4); \
    } while(0)
    #define STORET(b) do { \
        As[b][ac+0][ar]=a0v.x; As[b][ac+1][ar]=a0v.y; \
        As[b][ac+2][ar]=a0v.z; As[b][ac+3][ar]=a0v.w; \
        As[b][ac+4][ar]=a1v.x; As[b][ac+5][ar]=a1v.y; \
        As[b][ac+6][ar]=a1v.z; As[b][ac+7][ar]=a1v.w; \
        *(float4*)&Ws[b][wr][wc]   = w0v; \
        *(float4*)&Ws[b][wr][wc+4] = w1v; \
    } while(0)

    LOADT(0); STORET(0); __syncthreads();
    const int nt = K/16;
    for (int t = 0; t < nt; t++) {
        int cur = t & 1;
        if (t+1 < nt) LOADT((t+1)*16);
        #pragma unroll
        for (int kk = 0; kk < 16; kk++) {
            float4 af0 = *(float4*)&As[cur][kk][ty*8];
            float4 af1 = *(float4*)&As[cur][kk][ty*8+4];
            const u64* bp = (const u64*)&Ws[cur][kk][tx*8];
            u64 b2[4]; b2[0]=bp[0]; b2[1]=bp[1]; b2[2]=bp[2]; b2[3]=bp[3];
            u64 as2[8];
            as2[0]=pack2(af0.x,af0.x); as2[1]=pack2(af0.y,af0.y);
            as2[2]=pack2(af0.z,af0.z); as2[3]=pack2(af0.w,af0.w);
            as2[4]=pack2(af1.x,af1.x); as2[5]=pack2(af1.y,af1.y);
            as2[6]=pack2(af1.z,af1.z); as2[7]=pack2(af1.w,af1.w);
            #pragma unroll
            for (int i=0;i<8;i++)
                #pragma unroll
                for (int j=0;j<4;j++) fma2(acc[i][j], as2[i], b2[j]);
        }
        if (t+1 < nt) STORET(cur^1);
        __syncthreads();
    }
    #undef LOADT
    #undef STORET

    const int cn = bn + tx*8;
    float4 bv0 = *(const float4*)(bias + cn);
    float4 bv1 = *(const float4*)(bias + cn + 4);
    #pragma unroll
    for (int i = 0; i < 8; i++) {
        int cm = bm + ty*8 + i;
        float c[8];
        #pragma unroll
        for (int j=0;j<4;j++) unpack2(acc[i][j], c[2*j], c[2*j+1]);
        c[0]+=bv0.x; c[1]+=bv0.y; c[2]+=bv0.z; c[3]+=bv0.w;
        c[4]+=bv1.x; c[5]+=bv1.y; c[6]+=bv1.z; c[7]+=bv1.w;
        if (MODE==1 || MODE==2) {
            float4 r0 = *(const float4*)(R + (size_t)cm*Nc + cn);
            float4 r1 = *(const float4*)(R + (size_t)cm*Nc + cn + 4);
            c[0]+=r0.x; c[1]+=r0.y; c[2]+=r0.z; c[3]+=r0.w;
            c[4]+=r1.x; c[5]+=r1.y; c[6]+=r1.z; c[7]+=r1.w;
        }
        float4 o0 = make_float4(c[0],c[1],c[2],c[3]);
        float4 o1 = make_float4(c[4],c[5],c[6],c[7]);
        *(float4*)(C + (size_t)cm*Nc + cn)     = o0;
        *(float4*)(C + (size_t)cm*Nc + cn + 4) = o1;
    }
}

// ---------------- fused attention v3 ----------------
// Block: (b, head, 128-query tile), 256 threads, KT=128 key tiles (4 tiles).
// Warp w owns q-rows 16w..16w+15 END-TO-END (scores, softmax, P, PV, output).
// Lane owns keys {lane, lane+32, lane+64, lane+96}; scores per lane: 16r x 4k.
// Softmax running stats in warp-uniform registers (shfl-reduced). P written
// once as coalesced float4 in slot layout (slot = 4*lane+c); V stored slot-
// permuted to match. PV: 2 rows x 4 dims per lane, f32x2 packed over keys.
#define QT3 128
#define KT3 128
#define QP3 20
#define KP3 18
#define VP3 132
#define PP3 132

#define A_SM_QS 0
#define A_SM_KS (A_SM_QS + QT3*QP3)      // 2560
#define A_SM_VT (A_SM_KS + KT3*KP3)      // +2304
#define A_SM_P  (A_SM_VT + HDv*VP3)      // +2112
#define A_SM_L  (A_SM_P  + QT3*PP3)      // +16896
#define A_SM_DB (A_SM_L  + QT3)
#define A_SM_MK (A_SM_DB + 64)
#define A_SM_FLOATS (A_SM_MK + KT3)
#define A_SM_BYTES  (A_SM_FLOATS*4)      // ~96.8 KB

__global__ __launch_bounds__(256) void attn_kernel(
    const float* __restrict__ Q, const float* __restrict__ Kg,
    const float* __restrict__ V, const unsigned char* __restrict__ bins,
    const int* __restrict__ mask,
    const float* __restrict__ demb, const float* __restrict__ abias,
    float* __restrict__ AO)
{
    extern __shared__ __align__(16) float sm3[];
    float* Qs   = sm3 + A_SM_QS;
    float* Ks   = sm3 + A_SM_KS;
    float* Vt   = sm3 + A_SM_VT;
    float* P    = sm3 + A_SM_P;
    float* larr = sm3 + A_SM_L;
    float* db   = sm3 + A_SM_DB;
    int*  maskt = (int*)(sm3 + A_SM_MK);

    const int tid = threadIdx.x;
    const int w = tid >> 5, lane = tid & 31;
    const int qt = blockIdx.x, hh = blockIdx.y, bb = blockIdx.z;
    const int q0g = bb*Nv + qt*QT3;

    if (tid < NBINS) db[tid] = demb[tid*NHv + hh];
    {   // Q tile [128 x 16]
        int r = tid >> 1, j = (tid & 1) * 8;
        const float* qp_ = Q + (size_t)(q0g + r)*Hv + hh*HDv + j;
        *(float4*)&Qs[r*QP3 + j]     = *(const float4*)qp_;
        *(float4*)&Qs[r*QP3 + j + 4] = *(const float4*)(qp_ + 4);
    }
    const float ab = abias[hh];
    const int p = lane >> 2, g = lane & 3;

    float m_run[16], l_run[16];
    #pragma unroll
    for (int r=0;r<16;r++){ m_run[r]=-1e30f; l_run[r]=0.f; }
    u64 acc[2][4];
    #pragma unroll
    for (int i=0;i<2;i++)
        #pragma unroll
        for (int j=0;j<4;j++) acc[i][j]=0ull;

    for (int kt = 0; kt < Nv/KT3; kt++) {
        const int kb = kt*KT3;
        __syncthreads();   // guard Ks/Vt vs previous-iteration PV consumers
        // --- load K (row-major, KP3 stride) / V (slot-transposed) ---
        #pragma unroll
        for (int ii = 0; ii < 2; ii++) {
            int id = tid + ii*256;
            int r = id >> 2, j = (id & 3) << 2;
            size_t goff = (size_t)(bb*Nv + kb + r)*Hv + hh*HDv + j;
            float4 kv = *(const float4*)(Kg + goff);
            float* kd = &Ks[r*KP3 + j];
            *(float2*)kd     = make_float2(kv.x, kv.y);
            *(float2*)(kd+2) = make_float2(kv.z, kv.w);
            float4 vv = *(const float4*)(V + goff);
            int s = 4*(r & 31) + (r >> 5);   // slot of key r
            Vt[(j+0)*VP3 + s] = vv.x;
            Vt[(j+1)*VP3 + s] = vv.y;
            Vt[(j+2)*VP3 + s] = vv.z;
            Vt[(j+3)*VP3 + s] = vv.w;
        }
        if (tid < KT3) maskt[tid] = mask[bb*Nv + kb + tid];
        __syncthreads();

        // --- K rows for this lane's 4 keys into registers ---
        u64 kr0[8], kr1[8], kr2[8], kr3[8];
        {
            const u64* a0 = (const u64*)&Ks[(lane     )*KP3];
            const u64* a1 = (const u64*)&Ks[(lane + 32)*KP3];
            const u64* a2 = (const u64*)&Ks[(lane + 64)*KP3];
            const u64* a3 = (const u64*)&Ks[(lane + 96)*KP3];
            #pragma unroll
            for (int d=0; d<8; d++){ kr0[d]=a0[d]; kr1[d]=a1[d]; kr2[d]=a2[d]; kr3[d]=a3[d]; }
        }
        const bool mm0 = maskt[lane]      != 0;
        const bool mm1 = maskt[lane + 32] != 0;
        const bool mm2 = maskt[lane + 64] != 0;
        const bool mm3 = maskt[lane + 96] != 0;
        const unsigned char* bbase = bins + (size_t)(q0g + 16*w)*Nv + kb;

        #pragma unroll
        for (int r = 0; r < 16; r++) {
            const u64* qr = (const u64*)&Qs[(16*w + r)*QP3];
            u64 s0=0ull, s1=0ull, s2=0ull, s3=0ull;
            #pragma unroll
            for (int d=0; d<8; d++) {
                u64 qd = qr[d];
                fma2(s0, qd, kr0[d]); fma2(s1, qd, kr1[d]);
                fma2(s2, qd, kr2[d]); fma2(s3, qd, kr3[d]);
            }
            const unsigned char* brow = bbase + (size_t)r*Nv;
            float e, o, sc0, sc1, sc2, sc3;
            unpack2(s0,e,o); sc0 = (e+o)*0.25f;
            unpack2(s1,e,o); sc1 = (e+o)*0.25f;
            unpack2(s2,e,o); sc2 = (e+o)*0.25f;
            unpack2(s3,e,o); sc3 = (e+o)*0.25f;
            sc0 = mm0 ? -1e9f : sc0 + db[brow[lane     ]] + ab;
            sc1 = mm1 ? -1e9f : sc1 + db[brow[lane + 32]] + ab;
            sc2 = mm2 ? -1e9f : sc2 + db[brow[lane + 64]] + ab;
            sc3 = mm3 ? -1e9f : sc3 + db[brow[lane + 96]] + ab;
            float mt = fmaxf(fmaxf(sc0,sc1), fmaxf(sc2,sc3));
            #pragma unroll
            for (int off=16; off; off>>=1)
                mt = fmaxf(mt, __shfl_xor_sync(0xffffffffu, mt, off));
            float nm  = fmaxf(m_run[r], mt);
            float sco = __expf(m_run[r] - nm);
            float e0 = __expf(sc0 - nm);
            float e1 = __expf(sc1 - nm);
            float e2 = __expf(sc2 - nm);
            float e3 = __expf(sc3 - nm);
            float sum = (e0+e1) + (e2+e3);
            #pragma unroll
            for (int off=16; off; off>>=1)
                sum += __shfl_xor_sync(0xffffffffu, sum, off);
            l_run[r] = l_run[r]*sco + sum;
            m_run[r] = nm;
            if (lane == 0) larr[16*w + r] = l_run[r];
            *(float4*)&P[(16*w + r)*PP3 + 4*lane] = make_float4(e0,e1,e2,e3);
            // rescale this lane's PV accumulators when their row comes up
            u64 sc2p = pack2(sco, sco);
            if (r == 2*p) {
                acc[0][0]=mul2(acc[0][0],sc2p); acc[0][1]=mul2(acc[0][1],sc2p);
                acc[0][2]=mul2(acc[0][2],sc2p); acc[0][3]=mul2(acc[0][3],sc2p);
            }
            if (r == 2*p + 1) {
                acc[1][0]=mul2(acc[1][0],sc2p); acc[1][1]=mul2(acc[1][1],sc2p);
                acc[1][2]=mul2(acc[1][2],sc2p); acc[1][3]=mul2(acc[1][3],sc2p);
            }
        }
        __syncwarp();   // P rows of this warp written before PV reads them
        // --- PV: rows 16w+2p, +1; dims g, g+4, g+8, g+12 ---
        {
            const u64* pr0 = (const u64*)&P[(16*w + 2*p)*PP3];
            const u64* pr1 = pr0 + PP3/2;
            const u64* v0 = (const u64*)&Vt[(g     )*VP3];
            const u64* v1 = (const u64*)&Vt[(g +  4)*VP3];
            const u64* v2 = (const u64*)&Vt[(g +  8)*VP3];
            const u64* v3 = (const u64*)&Vt[(g + 12)*VP3];
            #pragma unroll 8
            for (int t = 0; t < KT3/2; t++) {
                u64 pa = pr0[t], pb = pr1[t];
                u64 va = v0[t], vb = v1[t], vc = v2[t], vd = v3[t];
                fma2(acc[0][0], pa, va); fma2(acc[0][1], pa, vb);
                fma2(acc[0][2], pa, vc); fma2(acc[0][3], pa, vd);
                fma2(acc[1][0], pb, va); fma2(acc[1][1], pb, vb);
                fma2(acc[1][2], pb, vc); fma2(acc[1][3], pb, vd);
            }
        }
    }
    __syncwarp();
    float invA = 1.0f / larr[16*w + 2*p];
    float invB = 1.0f / larr[16*w + 2*p + 1];
    float* oA = AO + (size_t)(q0g + 16*w + 2*p)*Hv + hh*HDv;
    float* oB = oA + Hv;
    #pragma unroll
    for (int dd = 0; dd < 4; dd++) {
        float e, o;
        unpack2(acc[0][dd], e, o); oA[g + 4*dd] = (e+o)*invA;
        unpack2(acc[1][dd], e, o); oB[g + 4*dd] = (e+o)*invB;
    }
}

// ---------------- launch ----------------
extern "C" void kernel_launch(void* const* d_in, const int* in_sizes, int n_in,
                              void* d_out, int out_size)
{
    const float* x    = (const float*)d_in[0];
    const float* dist = (const float*)d_in[1];
    const int*   mask = (const int*)d_in[2];
    const float* Wq  = (const float*)d_in[3];
    const float* bq  = (const float*)d_in[4];
    const float* Wk  = (const float*)d_in[5];
    const float* bk  = (const float*)d_in[6];
    const float* Wv  = (const float*)d_in[7];
    const float* bv  = (const float*)d_in[8];
    const float* Wo  = (const float*)d_in[9];
    const float* bo  = (const float*)d_in[10];
    const float* demb= (const float*)d_in[11];
    const float* ab  = (const float*)d_in[12];
    const float* g1  = (const float*)d_in[13];
    const float* b1  = (const float*)d_in[14];
    const float* g2  = (const float*)d_in[15];
    const float* b2  = (const float*)d_in[16];
    const float* Wf1 = (const float*)d_in[17];
    const float* bf1 = (const float*)d_in[18];
    const float* Wf2 = (const float*)d_in[19];
    const float* bf2 = (const float*)d_in[20];

    float* h = (float*)d_out;
    float *hn, *q, *k, *v, *ao, *u;
    unsigned char* bins;
    cudaGetSymbolAddress((void**)&hn, g_hn);
    cudaGetSymbolAddress((void**)&q,  g_q);
    cudaGetSymbolAddress((void**)&k,  g_k);
    cudaGetSymbolAddress((void**)&v,  g_v);
    cudaGetSymbolAddress((void**)&ao, g_ao);
    cudaGetSymbolAddress((void**)&u,  g_u);
    cudaGetSymbolAddress((void**)&bins, g_bins);

    cudaFuncSetAttribute(attn_kernel,
        cudaFuncAttributeMaxDynamicSharedMemorySize, A_SM_BYTES);

    cudaMemcpyAsync(h, x, (size_t)ROWS*Hv*sizeof(float), cudaMemcpyDeviceToDevice);
    bins_kernel<<<(ROWS*Nv)/1024, 256>>>(dist, bins);

    dim3 gqkv(3, ROWS/128);          // fused QKV
    dim3 gone(1, ROWS/128);          // N=128 GEMMs
    dim3 gff1(2*FFv/128, ROWS/128);  // (8, 128)
    dim3 gattn(Nv/QT3, NHv, Bv);     // (4, 8, 32)

    for (int l = 0; l < 3; l++) {
        ln_kernel<<<ROWS/8, 256>>>(h, g1 + l*Hv, b1 + l*Hv, hn);
        gemm_kernel<3><<<gqkv, 256>>>(hn,
            Wq + (size_t)l*Hv*Hv, bq + l*Hv, q,
            Wk + (size_t)l*Hv*Hv, bk + l*Hv, k,
            Wv + (size_t)l*Hv*Hv, bv + l*Hv, v,
            nullptr, Hv, Hv);
        attn_kernel<<<gattn, 256, A_SM_BYTES>>>(q, k, v, bins, mask,
                                    demb + (size_t)l*NBINS*NHv, ab + l*NHv, ao);
        gemm_kernel<1><<<gone, 256>>>(ao,
            Wo + (size_t)l*Hv*Hv, bo + l*Hv, h,
            nullptr, nullptr, nullptr, nullptr, nullptr, nullptr,
            h, Hv, Hv);
        ln_kernel<<<ROWS/8, 256>>>(h, g2 + l*Hv, b2 + l*Hv, hn);
        gemm_kernel<0><<<gff1, 256>>>(hn,
            Wf1 + (size_t)l*Hv*2*FFv, bf1 + (size_t)l*2*FFv, u,
            nullptr, nullptr, nullptr, nullptr, nullptr, nullptr,
            nullptr, Hv, 2*FFv);
        gemm_kernel<2><<<gone, 256>>>(u,
            Wf2 + (size_t)l*FFv*Hv, bf2 + l*Hv, h,
            nullptr, nullptr, nullptr, nullptr, nullptr, nullptr,
            h, FFv, Hv);
    }
}